// round 2
// baseline (speedup 1.0000x reference)
#include <cuda_runtime.h>
#include <math.h>
#include <stdint.h>

#define BB 2048
#define TT 256
#define NVF 32
#define HH 64
#define LL 32
#define OHH 64
#define G3 192

// ---------------- GRU config ----------------
#define GRU_BM 16
#define GRU_THREADS 384
#define GRU_BLOCKS (BB / GRU_BM)   // 128
// shared layout (floats): Wt[128*192] | Xs[128*16] | SI[16*196] | SH[16*196] | bih[192] | bhh[192] | slen(int16x?)
#define GRU_WT_OFF   0
#define GRU_XS_OFF   (128 * 192)
#define GRU_SI_OFF   (GRU_XS_OFF + 128 * 16)
#define GRU_SH_OFF   (GRU_SI_OFF + 16 * 196)
#define GRU_BIH_OFF  (GRU_SH_OFF + 16 * 196)
#define GRU_BHH_OFF  (GRU_BIH_OFF + 192)
#define GRU_SLEN_OFF (GRU_BHH_OFF + 192)
#define GRU_SMEM_FLOATS (GRU_SLEN_OFF + 16)
#define GRU_SMEM_BYTES (GRU_SMEM_FLOATS * 4)

// ---------------- ODE config ----------------
#define ODE_BM 16
#define ODE_THREADS 256
#define ODE_BLOCKS (BB / ODE_BM)   // 128
#define NSTEP 128
#define ODE_W1_OFF 0
#define ODE_W2_OFF (ODE_W1_OFF + 32 * 64)
#define ODE_W3_OFF (ODE_W2_OFF + 64 * 64)
#define ODE_B1_OFF (ODE_W3_OFF + 64 * 32)
#define ODE_B2_OFF (ODE_B1_OFF + 64)
#define ODE_B3_OFF (ODE_B2_OFF + 64)
#define ODE_ZC_OFF (ODE_B3_OFF + 32)
#define ODE_ZT_OFF (ODE_ZC_OFF + 512)
#define ODE_KS_OFF (ODE_ZT_OFF + 512)
#define ODE_KO_OFF (ODE_KS_OFF + 512)
#define ODE_H1_OFF (ODE_KO_OFF + 512)
#define ODE_H2_OFF (ODE_H1_OFF + 1024)
#define ODE_SMEM_FLOATS (ODE_H2_OFF + 1024)
#define ODE_SMEM_BYTES (ODE_SMEM_FLOATS * 4)

// ---------------- scratch (device globals; no allocations allowed) ----------------
__device__ float g_h[BB * HH];
__device__ float g_z0[BB * LL];
__device__ float g_zf[BB * LL];
__device__ float g_klb[BB];

__device__ __forceinline__ float fsig(float x) {
    return 1.0f / (1.0f + __expf(-x));
}
__device__ __forceinline__ float ftanh(float x) {
    x = fminf(15.0f, fmaxf(-15.0f, x));
    float e = __expf(2.0f * x);
    return __fdividef(e - 1.0f, e + 1.0f);
}

// =====================================================================
// GRU kernel: one block = 16 batches, persistent over time steps.
// Threads split: grp 0 accumulates the input projection (K = x features),
// grp 1 accumulates the hidden projection (K = h). 4g x 4b register tile.
// =====================================================================
extern "C" __global__ void __launch_bounds__(GRU_THREADS)
gru_kernel(const float* __restrict__ values, const float* __restrict__ mask,
           const int* __restrict__ seq_lengths,
           const float* __restrict__ W_ih, const float* __restrict__ W_hh,
           const float* __restrict__ b_ih, const float* __restrict__ b_hh)
{
    extern __shared__ float sm[];
    float* Wt  = sm + GRU_WT_OFF;   // [k 0..127][g 0..191]; k<64: W_ih, k>=64: W_hh
    float* Xs  = sm + GRU_XS_OFF;   // [k 0..127][b 0..15]; k<64: x_t, k>=64: h
    float* SI  = sm + GRU_SI_OFF;   // [b][196] : ih-part + b_ih
    float* SH  = sm + GRU_SH_OFF;   // [b][196] : hh-part + b_hh
    float* bih = sm + GRU_BIH_OFF;
    float* bhh = sm + GRU_BHH_OFF;
    int*   slen = (int*)(sm + GRU_SLEN_OFF);

    const int tid = threadIdx.x;
    const int b0blk = blockIdx.x * GRU_BM;

    // load weights transposed into SMEM
    for (int idx = tid; idx < G3 * 64; idx += GRU_THREADS) {
        int g = idx % G3, k = idx / G3;
        Wt[k * G3 + g]        = W_ih[g * 64 + k];
        Wt[(64 + k) * G3 + g] = W_hh[g * 64 + k];
    }
    for (int idx = tid; idx < G3; idx += GRU_THREADS) {
        bih[idx] = b_ih[idx];
        bhh[idx] = b_hh[idx];
    }
    if (tid < GRU_BM) slen[tid] = seq_lengths[b0blk + tid];
    // zero h (rows 64..127 of Xs)
    for (int idx = tid; idx < 64 * GRU_BM; idx += GRU_THREADS)
        Xs[64 * GRU_BM + idx] = 0.0f;
    __syncthreads();

    int Lmax = 0;
    #pragma unroll
    for (int i = 0; i < GRU_BM; i++) Lmax = max(Lmax, slen[i]);

    const int grp = tid / 192;          // 0: ih, 1: hh
    const int r   = tid % 192;
    const int g0  = (r % 48) * 4;
    const int bq  = (r / 48);
    const int b0  = bq * 4;
    const float* Wbase = Wt + grp * 64 * G3;
    const float* Xbase = Xs + grp * 64 * GRU_BM;
    float* Sout = grp ? SH : SI;
    const float* bsel = grp ? bhh : bih;

    for (int t = 0; t < Lmax; t++) {
        const int ti = TT - 1 - t;
        // load x_t (reversed time) into Xs rows 0..63
        for (int idx = tid; idx < 64 * GRU_BM; idx += GRU_THREADS) {
            int b = idx >> 6, f = idx & 63;
            int base = (b0blk + b) * TT * NVF + ti * NVF;
            float v = (f < NVF) ? values[base + f] : mask[base + (f - NVF)];
            Xs[f * GRU_BM + b] = v;
        }
        __syncthreads();

        float acc[4][4];
        #pragma unroll
        for (int i = 0; i < 4; i++)
            #pragma unroll
            for (int j = 0; j < 4; j++) acc[i][j] = 0.0f;

        #pragma unroll 16
        for (int k = 0; k < 64; k++) {
            float4 w = *(const float4*)(Wbase + k * G3 + g0);
            float4 x = *(const float4*)(Xbase + k * GRU_BM + b0);
            acc[0][0] += w.x * x.x; acc[0][1] += w.x * x.y; acc[0][2] += w.x * x.z; acc[0][3] += w.x * x.w;
            acc[1][0] += w.y * x.x; acc[1][1] += w.y * x.y; acc[1][2] += w.y * x.z; acc[1][3] += w.y * x.w;
            acc[2][0] += w.z * x.x; acc[2][1] += w.z * x.y; acc[2][2] += w.z * x.z; acc[2][3] += w.z * x.w;
            acc[3][0] += w.w * x.x; acc[3][1] += w.w * x.y; acc[3][2] += w.w * x.z; acc[3][3] += w.w * x.w;
        }
        float bb0 = bsel[g0 + 0], bb1 = bsel[g0 + 1], bb2 = bsel[g0 + 2], bb3 = bsel[g0 + 3];
        #pragma unroll
        for (int j = 0; j < 4; j++) {
            float4 v;
            v.x = acc[0][j] + bb0; v.y = acc[1][j] + bb1;
            v.z = acc[2][j] + bb2; v.w = acc[3][j] + bb3;
            *(float4*)&Sout[(b0 + j) * 196 + g0] = v;
        }
        __syncthreads();

        // gate combine + h update (1024 tasks)
        for (int idx = tid; idx < 64 * GRU_BM; idx += GRU_THREADS) {
            int b = idx & 15, j = idx >> 4;
            const float* si = &SI[b * 196];
            const float* sh = &SH[b * 196];
            float rg = fsig(si[j] + sh[j]);
            float zg = fsig(si[64 + j] + sh[64 + j]);
            float n  = ftanh(si[128 + j] + rg * sh[128 + j]);
            float hold = Xs[(64 + j) * GRU_BM + b];
            float hnew = (1.0f - zg) * n + zg * hold;
            if (t < slen[b]) Xs[(64 + j) * GRU_BM + b] = hnew;
        }
        __syncthreads();
    }

    // write final h (coalesced over j)
    for (int idx = tid; idx < 64 * GRU_BM; idx += GRU_THREADS) {
        int b = idx >> 6, j = idx & 63;
        g_h[(b0blk + b) * HH + j] = Xs[(64 + j) * GRU_BM + b];
    }
}

// =====================================================================
// z0 kernel: one block per batch, 64 threads.
// =====================================================================
extern "C" __global__ void __launch_bounds__(64)
z0_kernel(const float* __restrict__ W_z0, const float* __restrict__ b_z0,
          const float* __restrict__ eps)
{
    __shared__ float hs[64];
    __shared__ float zp[64];
    const int b = blockIdx.x;
    const int t = threadIdx.x;
    hs[t] = g_h[b * HH + t];
    __syncthreads();
    float s = b_z0[t];
    #pragma unroll 16
    for (int k = 0; k < 64; k++) s += W_z0[t * 64 + k] * hs[k];
    zp[t] = s;
    __syncthreads();
    if (t < 32) {
        float m = zp[t], lv = zp[32 + t];
        float z = m + eps[b * LL + t] * __expf(0.5f * lv);
        g_z0[b * LL + t] = z;
        float term = 1.0f + lv - m * m - __expf(lv);
        #pragma unroll
        for (int o = 16; o; o >>= 1) term += __shfl_down_sync(0xffffffffu, term, o);
        if (t == 0) g_klb[b] = term;
    }
}

// =====================================================================
// ODE kernel: RK4, 16 batches/block, staged SMEM mini-GEMMs.
// =====================================================================
__device__ __forceinline__ void ode_eval(const float* __restrict__ zin,
                                         float* __restrict__ h1, float* __restrict__ h2,
                                         float* __restrict__ ko,
                                         const float* __restrict__ W1t, const float* __restrict__ W2t,
                                         const float* __restrict__ W3t,
                                         const float* __restrict__ b1s, const float* __restrict__ b2s,
                                         const float* __restrict__ b3s,
                                         int u1, int bo1, int u3, int bo3)
{
    // stage 1: h1[64 x 16] = tanh(W1 z + b1), K = 32
    {
        float a0 = 0, a1 = 0, a2 = 0, a3 = 0;
        #pragma unroll
        for (int k = 0; k < 32; k++) {
            float w = W1t[k * 64 + u1];
            float4 x = *(const float4*)(zin + k * 16 + bo1);
            a0 += w * x.x; a1 += w * x.y; a2 += w * x.z; a3 += w * x.w;
        }
        float bb = b1s[u1];
        float4 v; v.x = ftanh(a0 + bb); v.y = ftanh(a1 + bb); v.z = ftanh(a2 + bb); v.w = ftanh(a3 + bb);
        *(float4*)&h1[u1 * 16 + bo1] = v;
    }
    __syncthreads();
    // stage 2: h2 = tanh(W2 h1 + b2), K = 64
    {
        float a0 = 0, a1 = 0, a2 = 0, a3 = 0;
        #pragma unroll 16
        for (int k = 0; k < 64; k++) {
            float w = W2t[k * 64 + u1];
            float4 x = *(const float4*)(h1 + k * 16 + bo1);
            a0 += w * x.x; a1 += w * x.y; a2 += w * x.z; a3 += w * x.w;
        }
        float bb = b2s[u1];
        float4 v; v.x = ftanh(a0 + bb); v.y = ftanh(a1 + bb); v.z = ftanh(a2 + bb); v.w = ftanh(a3 + bb);
        *(float4*)&h2[u1 * 16 + bo1] = v;
    }
    __syncthreads();
    // stage 3: ko[32 x 16] = W3 h2 + b3, K = 64
    {
        float a0 = 0, a1 = 0;
        #pragma unroll 16
        for (int k = 0; k < 64; k++) {
            float w = W3t[k * 32 + u3];
            float2 x = *(const float2*)(h2 + k * 16 + bo3);
            a0 += w * x.x; a1 += w * x.y;
        }
        float bb = b3s[u3];
        float2 v; v.x = a0 + bb; v.y = a1 + bb;
        *(float2*)&ko[u3 * 16 + bo3] = v;
    }
    __syncthreads();
}

extern "C" __global__ void __launch_bounds__(ODE_THREADS)
ode_kernel(const float* __restrict__ oW1, const float* __restrict__ ob1,
           const float* __restrict__ oW2, const float* __restrict__ ob2,
           const float* __restrict__ oW3, const float* __restrict__ ob3)
{
    extern __shared__ float sm[];
    float* W1t = sm + ODE_W1_OFF;   // [k<32][u<64]
    float* W2t = sm + ODE_W2_OFF;   // [k<64][u<64]
    float* W3t = sm + ODE_W3_OFF;   // [k<64][u<32]
    float* b1s = sm + ODE_B1_OFF;
    float* b2s = sm + ODE_B2_OFF;
    float* b3s = sm + ODE_B3_OFF;
    float* zc  = sm + ODE_ZC_OFF;   // [k<32][b<16]
    float* zt  = sm + ODE_ZT_OFF;
    float* ks  = sm + ODE_KS_OFF;
    float* ko  = sm + ODE_KO_OFF;
    float* h1  = sm + ODE_H1_OFF;
    float* h2  = sm + ODE_H2_OFF;

    const int tid = threadIdx.x;
    const int b0blk = blockIdx.x * ODE_BM;

    for (int idx = tid; idx < 32 * 64; idx += ODE_THREADS) {
        int u = idx & 63, k = idx >> 6;
        W1t[k * 64 + u] = oW1[u * 32 + k];
    }
    for (int idx = tid; idx < 64 * 64; idx += ODE_THREADS) {
        int u = idx & 63, k = idx >> 6;
        W2t[k * 64 + u] = oW2[u * 64 + k];
    }
    for (int idx = tid; idx < 64 * 32; idx += ODE_THREADS) {
        int u = idx & 31, k = idx >> 5;
        W3t[k * 32 + u] = oW3[u * 64 + k];
    }
    if (tid < 64) { b1s[tid] = ob1[tid]; b2s[tid] = ob2[tid]; }
    if (tid < 32) b3s[tid] = ob3[tid];
    for (int idx = tid; idx < 512; idx += ODE_THREADS) {
        int b = idx >> 5, k = idx & 31;
        zc[k * 16 + b] = g_z0[(b0blk + b) * LL + k];
    }
    __syncthreads();

    const int u1 = tid & 63, bo1 = (tid >> 6) * 4;
    const int u3 = tid & 31, bo3 = (tid >> 5) * 2;
    const float hstep = 48.0f / (float)NSTEP;

    for (int s = 0; s < NSTEP; s++) {
        ode_eval(zc, h1, h2, ko, W1t, W2t, W3t, b1s, b2s, b3s, u1, bo1, u3, bo3); // k1
        for (int idx = tid; idx < 512; idx += ODE_THREADS) {
            float kk = ko[idx]; ks[idx] = kk; zt[idx] = zc[idx] + 0.5f * hstep * kk;
        }
        __syncthreads();
        ode_eval(zt, h1, h2, ko, W1t, W2t, W3t, b1s, b2s, b3s, u1, bo1, u3, bo3); // k2
        for (int idx = tid; idx < 512; idx += ODE_THREADS) {
            float kk = ko[idx]; ks[idx] += 2.0f * kk; zt[idx] = zc[idx] + 0.5f * hstep * kk;
        }
        __syncthreads();
        ode_eval(zt, h1, h2, ko, W1t, W2t, W3t, b1s, b2s, b3s, u1, bo1, u3, bo3); // k3
        for (int idx = tid; idx < 512; idx += ODE_THREADS) {
            float kk = ko[idx]; ks[idx] += 2.0f * kk; zt[idx] = zc[idx] + hstep * kk;
        }
        __syncthreads();
        ode_eval(zt, h1, h2, ko, W1t, W2t, W3t, b1s, b2s, b3s, u1, bo1, u3, bo3); // k4
        for (int idx = tid; idx < 512; idx += ODE_THREADS) {
            zc[idx] += (hstep / 6.0f) * (ks[idx] + ko[idx]);
        }
        __syncthreads();
    }

    for (int idx = tid; idx < 512; idx += ODE_THREADS) {
        int b = idx >> 5, k = idx & 31;
        g_zf[(b0blk + b) * LL + k] = zc[k * 16 + b];
    }
}

// =====================================================================
// decoder: one block per batch, 64 threads
// =====================================================================
extern "C" __global__ void __launch_bounds__(64)
dec_kernel(const float* __restrict__ dW1, const float* __restrict__ db1,
           const float* __restrict__ dW2, const float* __restrict__ db2,
           float* __restrict__ out)
{
    __shared__ float zs[32];
    __shared__ float red[2];
    const int b = blockIdx.x;
    const int t = threadIdx.x;
    if (t < 32) zs[t] = g_zf[b * LL + t];
    __syncthreads();
    float s = db1[t];
    #pragma unroll
    for (int k = 0; k < 32; k++) s += dW1[t * 32 + k] * zs[k];
    s = fmaxf(s, 0.0f) * dW2[t];
    #pragma unroll
    for (int o = 16; o; o >>= 1) s += __shfl_down_sync(0xffffffffu, s, o);
    if ((t & 31) == 0) red[t >> 5] = s;
    __syncthreads();
    if (t == 0) out[b] = red[0] + red[1] + db2[0];
}

// =====================================================================
// KL finalize
// =====================================================================
extern "C" __global__ void __launch_bounds__(256)
kl_kernel(float* __restrict__ out, int out_size)
{
    __shared__ float red[256];
    const int t = threadIdx.x;
    float s = 0.0f;
    for (int i = t; i < BB; i += 256) s += g_klb[i];
    red[t] = s;
    __syncthreads();
    for (int o = 128; o; o >>= 1) {
        if (t < o) red[t] += red[t + o];
        __syncthreads();
    }
    if (t == 0 && out_size > BB)
        out[BB] = -0.5f * red[0] / (float)(BB * LL);
}

// =====================================================================
extern "C" void kernel_launch(void* const* d_in, const int* in_sizes, int n_in,
                              void* d_out, int out_size)
{
    const float* values = (const float*)d_in[1];
    const float* maskp  = (const float*)d_in[2];
    const int*   slen   = (const int*)d_in[3];
    const float* eps    = (const float*)d_in[4];
    const float* W_ih   = (const float*)d_in[5];
    const float* W_hh   = (const float*)d_in[6];
    const float* b_ih   = (const float*)d_in[7];
    const float* b_hh   = (const float*)d_in[8];
    const float* W_z0   = (const float*)d_in[9];
    const float* b_z0   = (const float*)d_in[10];
    const float* oW1    = (const float*)d_in[11];
    const float* ob1    = (const float*)d_in[12];
    const float* oW2    = (const float*)d_in[13];
    const float* ob2    = (const float*)d_in[14];
    const float* oW3    = (const float*)d_in[15];
    const float* ob3    = (const float*)d_in[16];
    const float* dW1    = (const float*)d_in[17];
    const float* db1    = (const float*)d_in[18];
    const float* dW2    = (const float*)d_in[19];
    const float* db2    = (const float*)d_in[20];
    float* out = (float*)d_out;

    cudaFuncSetAttribute(gru_kernel, cudaFuncAttributeMaxDynamicSharedMemorySize, GRU_SMEM_BYTES);
    cudaFuncSetAttribute(ode_kernel, cudaFuncAttributeMaxDynamicSharedMemorySize, ODE_SMEM_BYTES);

    gru_kernel<<<GRU_BLOCKS, GRU_THREADS, GRU_SMEM_BYTES>>>(values, maskp, slen,
                                                            W_ih, W_hh, b_ih, b_hh);
    z0_kernel<<<BB, 64>>>(W_z0, b_z0, eps);
    ode_kernel<<<ODE_BLOCKS, ODE_THREADS, ODE_SMEM_BYTES>>>(oW1, ob1, oW2, ob2, oW3, ob3);
    dec_kernel<<<BB, 64>>>(dW1, db1, dW2, db2, out);
    kl_kernel<<<1, 256>>>(out, out_size);
}

// round 3
// speedup vs baseline: 2.2820x; 2.2820x over previous
#include <cuda_runtime.h>
#include <math.h>
#include <stdint.h>

#define BB 2048
#define TT 256
#define NVF 32
#define HH 64
#define LL 32
#define OHH 64
#define G3 192

// ---------------- GRU config ----------------
#define GRU_BM 8
#define GRU_THREADS 256
#define GRU_BLOCKS (BB / GRU_BM)   // 256 blocks -> 2 waves, load-balanced by sorted lengths
// shared layout (floats)
#define GRU_WT_OFF   0
#define GRU_XS_OFF   (128 * G3)                      // 24576
#define GRU_SI_OFF   (GRU_XS_OFF + 128 * GRU_BM)     // + 1024
#define GRU_SH_OFF   (GRU_SI_OFF + GRU_BM * 196)
#define GRU_BIH_OFF  (GRU_SH_OFF + GRU_BM * 196)
#define GRU_BHH_OFF  (GRU_BIH_OFF + G3)
#define GRU_SLEN_OFF (GRU_BHH_OFF + G3)
#define GRU_SMEM_FLOATS (GRU_SLEN_OFF + GRU_BM)
#define GRU_SMEM_BYTES (GRU_SMEM_FLOATS * 4)

// ---------------- ODE config ----------------
#define ODE_BM 16
#define ODE_THREADS 256
#define ODE_BLOCKS (BB / ODE_BM)   // 128
#define NSTEP 32
#define ODE_W1_OFF 0
#define ODE_W2_OFF (ODE_W1_OFF + 32 * 64)
#define ODE_W3_OFF (ODE_W2_OFF + 64 * 64)
#define ODE_B1_OFF (ODE_W3_OFF + 64 * 32)
#define ODE_B2_OFF (ODE_B1_OFF + 64)
#define ODE_B3_OFF (ODE_B2_OFF + 64)
#define ODE_ZC_OFF (ODE_B3_OFF + 32)
#define ODE_ZT_OFF (ODE_ZC_OFF + 512)
#define ODE_KS_OFF (ODE_ZT_OFF + 512)
#define ODE_H1_OFF (ODE_KS_OFF + 512)
#define ODE_H2_OFF (ODE_H1_OFF + 1024)
#define ODE_SMEM_FLOATS (ODE_H2_OFF + 1024)
#define ODE_SMEM_BYTES (ODE_SMEM_FLOATS * 4)

// ---------------- scratch (device globals; no allocations allowed) ----------------
__device__ float g_h[BB * HH];
__device__ float g_z0[BB * LL];
__device__ float g_zf[BB * LL];
__device__ float g_klb[BB];

__device__ __forceinline__ float fsig(float x) {
    return 1.0f / (1.0f + __expf(-x));
}
__device__ __forceinline__ float ftanh(float x) {
    x = fminf(15.0f, fmaxf(-15.0f, x));
    float e = __expf(2.0f * x);
    return __fdividef(e - 1.0f, e + 1.0f);
}

// =====================================================================
// GRU kernel: one block = 8 batches, persistent over time steps.
// 192 compute threads: grp 0 (ih proj, K = x), grp 1 (hh proj, K = h),
// 4g x 4b register tiles. x_{t+1} prefetched into registers under the GEMM.
// =====================================================================
extern "C" __global__ void __launch_bounds__(GRU_THREADS)
gru_kernel(const float* __restrict__ values, const float* __restrict__ mask,
           const int* __restrict__ seq_lengths,
           const float* __restrict__ W_ih, const float* __restrict__ W_hh,
           const float* __restrict__ b_ih, const float* __restrict__ b_hh)
{
    extern __shared__ float sm[];
    float* Wt  = sm + GRU_WT_OFF;   // [k 0..127][g 0..191]; k<64: W_ih, k>=64: W_hh
    float* Xs  = sm + GRU_XS_OFF;   // [k 0..127][b 0..7]; k<64: x_t, k>=64: h
    float* SI  = sm + GRU_SI_OFF;   // [b][196]
    float* SH  = sm + GRU_SH_OFF;   // [b][196]
    float* bih = sm + GRU_BIH_OFF;
    float* bhh = sm + GRU_BHH_OFF;
    int*   slen = (int*)(sm + GRU_SLEN_OFF);

    const int tid = threadIdx.x;
    const int b0blk = blockIdx.x * GRU_BM;

    for (int idx = tid; idx < G3 * 64; idx += GRU_THREADS) {
        int g = idx % G3, k = idx / G3;
        Wt[k * G3 + g]        = W_ih[g * 64 + k];
        Wt[(64 + k) * G3 + g] = W_hh[g * 64 + k];
    }
    if (tid < G3) { bih[tid] = b_ih[tid]; bhh[tid] = b_hh[tid]; }
    if (tid < GRU_BM) slen[tid] = seq_lengths[b0blk + tid];
    for (int idx = tid; idx < 64 * GRU_BM; idx += GRU_THREADS)
        Xs[64 * GRU_BM + idx] = 0.0f;
    __syncthreads();

    int Lmax = 0;
    #pragma unroll
    for (int i = 0; i < GRU_BM; i++) Lmax = max(Lmax, slen[i]);

    // compute-thread mapping (tid < 192)
    const int grp = tid / 96;              // 0: ih, 1: hh  (garbage for tid>=192, unused)
    const int r   = tid % 96;
    const int g0  = (r % 48) * 4;
    const int b0  = (r / 48) * 4;
    const float* Wbase = Wt + grp * 64 * G3;
    const float* Xbase = Xs + grp * 64 * GRU_BM;
    float* Sout = grp ? SH : SI;
    const float* bsel = grp ? bhh : bih;

    // x prefetch: 512 elements, 2 per thread (idx = tid, tid+256)
    const int pf_b0 = tid >> 6,      pf_f0 = tid & 63;
    const int pf_b1 = (tid + 256) >> 6, pf_f1 = (tid + 256) & 63;
    const int base0 = (b0blk + pf_b0) * TT * NVF;
    const int base1 = (b0blk + pf_b1) * TT * NVF;
    float px0, px1;
    {
        const int ti = TT - 1;
        px0 = (pf_f0 < NVF) ? values[base0 + ti * NVF + pf_f0] : mask[base0 + ti * NVF + pf_f0 - NVF];
        px1 = (pf_f1 < NVF) ? values[base1 + ti * NVF + pf_f1] : mask[base1 + ti * NVF + pf_f1 - NVF];
    }

    for (int t = 0; t < Lmax; t++) {
        // commit prefetched x_t
        Xs[pf_f0 * GRU_BM + pf_b0] = px0;
        Xs[pf_f1 * GRU_BM + pf_b1] = px1;
        __syncthreads();

        // prefetch x_{t+1} (hidden under the GEMM)
        if (t + 1 < Lmax) {
            const int ti = TT - 2 - t;
            px0 = (pf_f0 < NVF) ? values[base0 + ti * NVF + pf_f0] : mask[base0 + ti * NVF + pf_f0 - NVF];
            px1 = (pf_f1 < NVF) ? values[base1 + ti * NVF + pf_f1] : mask[base1 + ti * NVF + pf_f1 - NVF];
        }

        if (tid < 192) {
            float acc[4][4];
            #pragma unroll
            for (int i = 0; i < 4; i++)
                #pragma unroll
                for (int j = 0; j < 4; j++) acc[i][j] = 0.0f;

            #pragma unroll 16
            for (int k = 0; k < 64; k++) {
                float4 w = *(const float4*)(Wbase + k * G3 + g0);
                float4 x = *(const float4*)(Xbase + k * GRU_BM + b0);
                acc[0][0] += w.x * x.x; acc[0][1] += w.x * x.y; acc[0][2] += w.x * x.z; acc[0][3] += w.x * x.w;
                acc[1][0] += w.y * x.x; acc[1][1] += w.y * x.y; acc[1][2] += w.y * x.z; acc[1][3] += w.y * x.w;
                acc[2][0] += w.z * x.x; acc[2][1] += w.z * x.y; acc[2][2] += w.z * x.z; acc[2][3] += w.z * x.w;
                acc[3][0] += w.w * x.x; acc[3][1] += w.w * x.y; acc[3][2] += w.w * x.z; acc[3][3] += w.w * x.w;
            }
            float bb0 = bsel[g0 + 0], bb1 = bsel[g0 + 1], bb2 = bsel[g0 + 2], bb3 = bsel[g0 + 3];
            #pragma unroll
            for (int j = 0; j < 4; j++) {
                float4 v;
                v.x = acc[0][j] + bb0; v.y = acc[1][j] + bb1;
                v.z = acc[2][j] + bb2; v.w = acc[3][j] + bb3;
                *(float4*)&Sout[(b0 + j) * 196 + g0] = v;
            }
        }
        __syncthreads();

        // gate combine + h update (512 tasks)
        for (int idx = tid; idx < 64 * GRU_BM; idx += GRU_THREADS) {
            int b = idx & (GRU_BM - 1), j = idx >> 3;
            const float* si = &SI[b * 196];
            const float* sh = &SH[b * 196];
            float rg = fsig(si[j] + sh[j]);
            float zg = fsig(si[64 + j] + sh[64 + j]);
            float n  = ftanh(si[128 + j] + rg * sh[128 + j]);
            float hold = Xs[(64 + j) * GRU_BM + b];
            float hnew = (1.0f - zg) * n + zg * hold;
            if (t < slen[b]) Xs[(64 + j) * GRU_BM + b] = hnew;
        }
        __syncthreads();
    }

    for (int idx = tid; idx < 64 * GRU_BM; idx += GRU_THREADS) {
        int b = idx >> 6, j = idx & 63;
        g_h[(b0blk + b) * HH + j] = Xs[(64 + j) * GRU_BM + b];
    }
}

// =====================================================================
// z0 kernel: one block per batch, 64 threads.
// =====================================================================
extern "C" __global__ void __launch_bounds__(64)
z0_kernel(const float* __restrict__ W_z0, const float* __restrict__ b_z0,
          const float* __restrict__ eps)
{
    __shared__ float hs[64];
    __shared__ float zp[64];
    const int b = blockIdx.x;
    const int t = threadIdx.x;
    hs[t] = g_h[b * HH + t];
    __syncthreads();
    float s = b_z0[t];
    #pragma unroll 16
    for (int k = 0; k < 64; k++) s += W_z0[t * 64 + k] * hs[k];
    zp[t] = s;
    __syncthreads();
    if (t < 32) {
        float m = zp[t], lv = zp[32 + t];
        float z = m + eps[b * LL + t] * __expf(0.5f * lv);
        g_z0[b * LL + t] = z;
        float term = 1.0f + lv - m * m - __expf(lv);
        #pragma unroll
        for (int o = 16; o; o >>= 1) term += __shfl_down_sync(0xffffffffu, term, o);
        if (t == 0) g_klb[b] = term;
    }
}

// =====================================================================
// ODE kernel: RK4, 16 batches/block. RK combine fused into stage 3.
// =====================================================================
template <int MODE>
__device__ __forceinline__ void ode_eval(const float* __restrict__ zin,
                                         float* __restrict__ zc, float* __restrict__ zt,
                                         float* __restrict__ ks,
                                         float* __restrict__ h1, float* __restrict__ h2,
                                         const float* __restrict__ W1t, const float* __restrict__ W2t,
                                         const float* __restrict__ W3t,
                                         const float* __restrict__ b1s, const float* __restrict__ b2s,
                                         const float* __restrict__ b3s,
                                         int u1, int bo1, int u3, int bo3, float hstep)
{
    // stage 1: h1[64 x 16] = tanh(W1 z + b1), K = 32
    {
        float a0 = 0, a1 = 0, a2 = 0, a3 = 0;
        #pragma unroll
        for (int k = 0; k < 32; k++) {
            float w = W1t[k * 64 + u1];
            float4 x = *(const float4*)(zin + k * 16 + bo1);
            a0 += w * x.x; a1 += w * x.y; a2 += w * x.z; a3 += w * x.w;
        }
        float bb = b1s[u1];
        float4 v; v.x = ftanh(a0 + bb); v.y = ftanh(a1 + bb); v.z = ftanh(a2 + bb); v.w = ftanh(a3 + bb);
        *(float4*)&h1[u1 * 16 + bo1] = v;
    }
    __syncthreads();
    // stage 2: h2 = tanh(W2 h1 + b2), K = 64
    {
        float a0 = 0, a1 = 0, a2 = 0, a3 = 0;
        #pragma unroll 16
        for (int k = 0; k < 64; k++) {
            float w = W2t[k * 64 + u1];
            float4 x = *(const float4*)(h1 + k * 16 + bo1);
            a0 += w * x.x; a1 += w * x.y; a2 += w * x.z; a3 += w * x.w;
        }
        float bb = b2s[u1];
        float4 v; v.x = ftanh(a0 + bb); v.y = ftanh(a1 + bb); v.z = ftanh(a2 + bb); v.w = ftanh(a3 + bb);
        *(float4*)&h2[u1 * 16 + bo1] = v;
    }
    __syncthreads();
    // stage 3: k[32 x 16] = W3 h2 + b3, K = 64, fused RK combine
    {
        float a0 = 0, a1 = 0;
        #pragma unroll 16
        for (int k = 0; k < 64; k++) {
            float w = W3t[k * 32 + u3];
            float2 x = *(const float2*)(h2 + k * 16 + bo3);
            a0 += w * x.x; a1 += w * x.y;
        }
        float bb = b3s[u3];
        float k0 = a0 + bb, k1 = a1 + bb;
        const int i0 = u3 * 16 + bo3, i1 = i0 + 1;
        if (MODE == 0) {
            ks[i0] = k0;             ks[i1] = k1;
            zt[i0] = zc[i0] + 0.5f * hstep * k0;
            zt[i1] = zc[i1] + 0.5f * hstep * k1;
        } else if (MODE == 1) {
            ks[i0] += 2.0f * k0;     ks[i1] += 2.0f * k1;
            zt[i0] = zc[i0] + 0.5f * hstep * k0;
            zt[i1] = zc[i1] + 0.5f * hstep * k1;
        } else if (MODE == 2) {
            ks[i0] += 2.0f * k0;     ks[i1] += 2.0f * k1;
            zt[i0] = zc[i0] + hstep * k0;
            zt[i1] = zc[i1] + hstep * k1;
        } else {
            zc[i0] += (hstep / 6.0f) * (ks[i0] + k0);
            zc[i1] += (hstep / 6.0f) * (ks[i1] + k1);
        }
    }
    __syncthreads();
}

extern "C" __global__ void __launch_bounds__(ODE_THREADS)
ode_kernel(const float* __restrict__ oW1, const float* __restrict__ ob1,
           const float* __restrict__ oW2, const float* __restrict__ ob2,
           const float* __restrict__ oW3, const float* __restrict__ ob3)
{
    extern __shared__ float sm[];
    float* W1t = sm + ODE_W1_OFF;
    float* W2t = sm + ODE_W2_OFF;
    float* W3t = sm + ODE_W3_OFF;
    float* b1s = sm + ODE_B1_OFF;
    float* b2s = sm + ODE_B2_OFF;
    float* b3s = sm + ODE_B3_OFF;
    float* zc  = sm + ODE_ZC_OFF;
    float* zt  = sm + ODE_ZT_OFF;
    float* ks  = sm + ODE_KS_OFF;
    float* h1  = sm + ODE_H1_OFF;
    float* h2  = sm + ODE_H2_OFF;

    const int tid = threadIdx.x;
    const int b0blk = blockIdx.x * ODE_BM;

    for (int idx = tid; idx < 32 * 64; idx += ODE_THREADS) {
        int u = idx & 63, k = idx >> 6;
        W1t[k * 64 + u] = oW1[u * 32 + k];
    }
    for (int idx = tid; idx < 64 * 64; idx += ODE_THREADS) {
        int u = idx & 63, k = idx >> 6;
        W2t[k * 64 + u] = oW2[u * 64 + k];
    }
    for (int idx = tid; idx < 64 * 32; idx += ODE_THREADS) {
        int u = idx & 31, k = idx >> 5;
        W3t[k * 32 + u] = oW3[u * 64 + k];
    }
    if (tid < 64) { b1s[tid] = ob1[tid]; b2s[tid] = ob2[tid]; }
    if (tid < 32) b3s[tid] = ob3[tid];
    for (int idx = tid; idx < 512; idx += ODE_THREADS) {
        int b = idx >> 5, k = idx & 31;
        zc[k * 16 + b] = g_z0[(b0blk + b) * LL + k];
    }
    __syncthreads();

    const int u1 = tid & 63, bo1 = (tid >> 6) * 4;
    const int u3 = tid & 31, bo3 = (tid >> 5) * 2;
    const float hstep = 48.0f / (float)NSTEP;

    for (int s = 0; s < NSTEP; s++) {
        ode_eval<0>(zc, zc, zt, ks, h1, h2, W1t, W2t, W3t, b1s, b2s, b3s, u1, bo1, u3, bo3, hstep);
        ode_eval<1>(zt, zc, zt, ks, h1, h2, W1t, W2t, W3t, b1s, b2s, b3s, u1, bo1, u3, bo3, hstep);
        ode_eval<2>(zt, zc, zt, ks, h1, h2, W1t, W2t, W3t, b1s, b2s, b3s, u1, bo1, u3, bo3, hstep);
        ode_eval<3>(zt, zc, zt, ks, h1, h2, W1t, W2t, W3t, b1s, b2s, b3s, u1, bo1, u3, bo3, hstep);
    }

    for (int idx = tid; idx < 512; idx += ODE_THREADS) {
        int b = idx >> 5, k = idx & 31;
        g_zf[(b0blk + b) * LL + k] = zc[k * 16 + b];
    }
}

// =====================================================================
// decoder: one block per batch, 64 threads
// =====================================================================
extern "C" __global__ void __launch_bounds__(64)
dec_kernel(const float* __restrict__ dW1, const float* __restrict__ db1,
           const float* __restrict__ dW2, const float* __restrict__ db2,
           float* __restrict__ out)
{
    __shared__ float zs[32];
    __shared__ float red[2];
    const int b = blockIdx.x;
    const int t = threadIdx.x;
    if (t < 32) zs[t] = g_zf[b * LL + t];
    __syncthreads();
    float s = db1[t];
    #pragma unroll
    for (int k = 0; k < 32; k++) s += dW1[t * 32 + k] * zs[k];
    s = fmaxf(s, 0.0f) * dW2[t];
    #pragma unroll
    for (int o = 16; o; o >>= 1) s += __shfl_down_sync(0xffffffffu, s, o);
    if ((t & 31) == 0) red[t >> 5] = s;
    __syncthreads();
    if (t == 0) out[b] = red[0] + red[1] + db2[0];
}

// =====================================================================
// KL finalize
// =====================================================================
extern "C" __global__ void __launch_bounds__(256)
kl_kernel(float* __restrict__ out, int out_size)
{
    __shared__ float red[256];
    const int t = threadIdx.x;
    float s = 0.0f;
    for (int i = t; i < BB; i += 256) s += g_klb[i];
    red[t] = s;
    __syncthreads();
    for (int o = 128; o; o >>= 1) {
        if (t < o) red[t] += red[t + o];
        __syncthreads();
    }
    if (t == 0 && out_size > BB)
        out[BB] = -0.5f * red[0] / (float)(BB * LL);
}

// =====================================================================
extern "C" void kernel_launch(void* const* d_in, const int* in_sizes, int n_in,
                              void* d_out, int out_size)
{
    const float* values = (const float*)d_in[1];
    const float* maskp  = (const float*)d_in[2];
    const int*   slen   = (const int*)d_in[3];
    const float* eps    = (const float*)d_in[4];
    const float* W_ih   = (const float*)d_in[5];
    const float* W_hh   = (const float*)d_in[6];
    const float* b_ih   = (const float*)d_in[7];
    const float* b_hh   = (const float*)d_in[8];
    const float* W_z0   = (const float*)d_in[9];
    const float* b_z0   = (const float*)d_in[10];
    const float* oW1    = (const float*)d_in[11];
    const float* ob1    = (const float*)d_in[12];
    const float* oW2    = (const float*)d_in[13];
    const float* ob2    = (const float*)d_in[14];
    const float* oW3    = (const float*)d_in[15];
    const float* ob3    = (const float*)d_in[16];
    const float* dW1    = (const float*)d_in[17];
    const float* db1    = (const float*)d_in[18];
    const float* dW2    = (const float*)d_in[19];
    const float* db2    = (const float*)d_in[20];
    float* out = (float*)d_out;

    cudaFuncSetAttribute(gru_kernel, cudaFuncAttributeMaxDynamicSharedMemorySize, GRU_SMEM_BYTES);
    cudaFuncSetAttribute(ode_kernel, cudaFuncAttributeMaxDynamicSharedMemorySize, ODE_SMEM_BYTES);

    gru_kernel<<<GRU_BLOCKS, GRU_THREADS, GRU_SMEM_BYTES>>>(values, maskp, slen,
                                                            W_ih, W_hh, b_ih, b_hh);
    z0_kernel<<<BB, 64>>>(W_z0, b_z0, eps);
    ode_kernel<<<ODE_BLOCKS, ODE_THREADS, ODE_SMEM_BYTES>>>(oW1, ob1, oW2, ob2, oW3, ob3);
    dec_kernel<<<BB, 64>>>(dW1, db1, dW2, db2, out);
    kl_kernel<<<1, 256>>>(out, out_size);
}